// round 7
// baseline (speedup 1.0000x reference)
#include <cuda_runtime.h>
#include <cuda_bf16.h>
#include <cstdint>
#include <cstring>

// involution: B=4, C=256, G=16, K=7, S=1, P=3, R=4, H=W=56
#define BB   4
#define CC   256
#define GG   16
#define CPG  16
#define KF   7
#define PAD  3
#define HH   56
#define WW   56
#define CR   64      // C/R
#define KK   49
#define KKG  784     // K*K*G
#define TW   28
#define TQ   (TW/4)
#define NTHREADS 256

#define XSC   128
#define XWC   16
#define XWW   36

// ---- smem map (float units) ----
// ks [784][28] f32 ............ 0      .. 21952
// region R (time-shared):
//   xs  [128][28] f32 (3584) / hsb hi+lo (2*1152) / xw [16][7][36] (4032)
#define R_OFF      21952
#define R_FLOATS   4032
#define HS_OFF     (R_OFF + R_FLOATS)        // hs [64][28] f32
#define SMEM_FLOATS (HS_OFF + CR * TW)       // 27776 floats = 111104 B

#define HSB_STRIDE 72                        // bf16 elements per n-row (conflict-free)

// pre-split sw in mma A-fragment order: [hi/lo][tile*4+ktile][lane] uint4
__device__ __align__(16) uint4 g_A[2][196][32];

__device__ __forceinline__ unsigned short bfbits(__nv_bfloat16 h) {
    unsigned short s; memcpy(&s, &h, 2); return s;
}

__device__ __forceinline__ void mma_bf16(float* c, const uint4& a,
                                         unsigned b0, unsigned b1) {
    asm volatile(
        "mma.sync.aligned.m16n8k16.row.col.f32.bf16.bf16.f32 "
        "{%0,%1,%2,%3}, {%4,%5,%6,%7}, {%8,%9}, {%0,%1,%2,%3};"
        : "+f"(c[0]), "+f"(c[1]), "+f"(c[2]), "+f"(c[3])
        : "r"(a.x), "r"(a.y), "r"(a.z), "r"(a.w), "r"(b0), "r"(b1));
}

// ---------------- prep: split sw into bf16 hi/lo A-fragments ----------------
__global__ void prep_sw_kernel(const float* __restrict__ sw)
{
    int i = blockIdx.x * blockDim.x + threadIdx.x;
    if (i >= 196 * 32) return;
    int tu = i >> 5, lane = i & 31;
    int t = tu >> 2, u = tu & 3;
    int r0 = t * 16 + (lane >> 2);
    int c0 = u * 16 + (lane & 3) * 2;
    const int rr[4] = {r0, r0 + 8, r0, r0 + 8};
    const int cc[4] = {c0, c0, c0 + 8, c0 + 8};
    unsigned hv[4], lv[4];
    #pragma unroll
    for (int j = 0; j < 4; j++) {
        float v0 = sw[rr[j] * CR + cc[j]];
        float v1 = sw[rr[j] * CR + cc[j] + 1];
        __nv_bfloat16 h0 = __float2bfloat16(v0);
        __nv_bfloat16 h1 = __float2bfloat16(v1);
        __nv_bfloat16 l0 = __float2bfloat16(v0 - __bfloat162float(h0));
        __nv_bfloat16 l1 = __float2bfloat16(v1 - __bfloat162float(h1));
        hv[j] = (unsigned)bfbits(h0) | ((unsigned)bfbits(h1) << 16);
        lv[j] = (unsigned)bfbits(l0) | ((unsigned)bfbits(l1) << 16);
    }
    g_A[0][tu][lane] = make_uint4(hv[0], hv[1], hv[2], hv[3]);
    g_A[1][tu][lane] = make_uint4(lv[0], lv[1], lv[2], lv[3]);
}

// ---------------- main fused kernel ----------------
__global__ __launch_bounds__(NTHREADS, 2)
void inv_fused_kernel(const float* __restrict__ x,
                      const float* __restrict__ rw,   // [CR][C]
                      const float* __restrict__ rb,   // [CR]
                      const float* __restrict__ sb,   // [KKG]
                      float* __restrict__ out)
{
    extern __shared__ __align__(16) float smem[];
    float* ks = smem;                        // [KKG][TW]
    float* xs = smem + R_OFF;                // [128][28]
    float* hs = smem + HS_OFF;               // [64][28] k-major
    float* xw = smem + R_OFF;                // [16][7][36] (P4, overlays xs/hsb)
    __nv_bfloat16* hb = (__nv_bfloat16*)(smem + R_OFF);        // [32][72]
    __nv_bfloat16* lb = hb + 32 * HSB_STRIDE;                  // [32][72]
    float4* xs4  = (float4*)xs;
    float4* rws4 = (float4*)ks;              // staged rw (pre-P3)

    const int x0   = blockIdx.x * TW;
    const int y    = blockIdx.y;
    const int b    = blockIdx.z;
    const int tid  = threadIdx.x;
    const int warp = tid >> 5;               // 0..7
    const int lane = tid & 31;

    // ---- Phase 0: stage rw[64][256] into smem (ks area) ----
    {
        const float4* rwg4 = (const float4*)rw;
        #pragma unroll
        for (int i = tid; i < (CR * CC) / 4; i += NTHREADS)
            rws4[i] = rwg4[i];
    }

    // ---- Phase 1+2: hs[k][px] = sum_c rw[k][c]*x[c][px] + rb[k] ----
    {
        float acc[8];
        #pragma unroll
        for (int j = 0; j < 8; j++) acc[j] = 0.f;
        const int o0 = warp * 8;

        #pragma unroll
        for (int half = 0; half < 2; half++) {
            if (half) __syncthreads();       // WAR on xs
            {
                const float4* xg4 = (const float4*)
                    (x + ((size_t)(b * CC + half * XSC) * HH + y) * WW + x0);
                const int cstride4 = (HH * WW) / 4;
                #pragma unroll
                for (int idx = tid; idx < XSC * TQ; idx += NTHREADS) {
                    int c = idx / TQ;
                    int q = idx - c * TQ;
                    xs4[c * TQ + q] = xg4[(size_t)c * cstride4 + q];
                }
            }
            __syncthreads();

            if (lane < TW) {
                #pragma unroll 2
                for (int kq = 0; kq < XSC / 4; kq++) {
                    float v0 = xs[(4 * kq + 0) * TW + lane];
                    float v1 = xs[(4 * kq + 1) * TW + lane];
                    float v2 = xs[(4 * kq + 2) * TW + lane];
                    float v3 = xs[(4 * kq + 3) * TW + lane];
                    #pragma unroll
                    for (int j = 0; j < 8; j++) {
                        float4 w = rws4[(o0 + j) * (CC / 4) + half * (XSC / 4) + kq];
                        acc[j] += w.x * v0 + w.y * v1 + w.z * v2 + w.w * v3;
                    }
                }
            }
        }
        if (lane < TW) {
            #pragma unroll
            for (int j = 0; j < 8; j++)
                hs[(o0 + j) * TW + lane] = acc[j] + rb[o0 + j];
        }
    }
    __syncthreads();   // hs ready; rw-in-ks dead; xs dead

    // ---- Build B panel: hs -> bf16 hi/lo, [32 n][72 k] ----
    {
        #pragma unroll
        for (int i = tid; i < 32 * CR; i += NTHREADS) {
            int n = i >> 6, k = i & 63;
            float v = (n < TW) ? hs[k * TW + n] : 0.f;
            __nv_bfloat16 h = __float2bfloat16(v);
            __nv_bfloat16 l = __float2bfloat16(v - __bfloat162float(h));
            hb[n * HSB_STRIDE + k] = h;
            lb[n * HSB_STRIDE + k] = l;
        }
    }
    __syncthreads();

    // ---- Phase 3 (HMMA): ks[784][28] = sw @ hs + sb ----
    // warp handles m16-tiles t = warp, warp+8, ... (49 tiles total)
    #pragma unroll 1
    for (int t = warp; t < 49; t += 8) {
        uint4 ah[4], al[4];
        #pragma unroll
        for (int u = 0; u < 4; u++) {
            ah[u] = g_A[0][t * 4 + u][lane];
            al[u] = g_A[1][t * 4 + u][lane];
        }
        const int r0 = t * 16 + (lane >> 2);
        const float bias0 = sb[r0];
        const float bias1 = sb[r0 + 8];

        float acc[4][4];
        #pragma unroll
        for (int v = 0; v < 4; v++) {
            acc[v][0] = bias0; acc[v][1] = bias0;
            acc[v][2] = bias1; acc[v][3] = bias1;
        }

        #pragma unroll
        for (int v = 0; v < 4; v++) {
            const int n = v * 8 + (lane >> 2);
            const __nv_bfloat16* hrow = hb + n * HSB_STRIDE;
            const __nv_bfloat16* lrow = lb + n * HSB_STRIDE;
            #pragma unroll
            for (int u = 0; u < 4; u++) {
                const int k0 = u * 16 + (lane & 3) * 2;
                unsigned bh0 = *(const unsigned*)(hrow + k0);
                unsigned bh1 = *(const unsigned*)(hrow + k0 + 8);
                unsigned bl0 = *(const unsigned*)(lrow + k0);
                unsigned bl1 = *(const unsigned*)(lrow + k0 + 8);
                mma_bf16(acc[v], ah[u], bh0, bh1);   // hi*hi
                mma_bf16(acc[v], ah[u], bl0, bl1);   // hi*lo
                mma_bf16(acc[v], al[u], bh0, bh1);   // lo*hi
            }
        }

        #pragma unroll
        for (int v = 0; v < 4; v++) {
            const int px0 = v * 8 + (lane & 3) * 2;
            if (px0 < TW) {
                *(float2*)(ks + (size_t)r0 * TW + px0) =
                    make_float2(acc[v][0], acc[v][1]);
                *(float2*)(ks + (size_t)(r0 + 8) * TW + px0) =
                    make_float2(acc[v][2], acc[v][3]);
            }
        }
    }
    __syncthreads();   // ks complete; hsb dead (xw overlays)

    // ---- Phase 4: involution apply ----
    #pragma unroll
    for (int s = 0; s < 2; s++) {
        const int g = 8 * s + warp;
        float kr[KK];
        if (lane < TW) {
            const float* kb = ks + g * KK * TW + lane;
            #pragma unroll
            for (int t = 0; t < KK; t++) kr[t] = kb[t * TW];
        }

        #pragma unroll 1
        for (int j = 0; j < 8; j++) {
            __syncthreads();   // WAR on xw
            {
                float4* xw4 = (float4*)xw;
                const float4 zero4 = make_float4(0.f, 0.f, 0.f, 0.f);
                #pragma unroll
                for (int idx = tid; idx < XWC * KF * (XWW / 4); idx += NTHREADS) {
                    int slot = idx / (KF * (XWW / 4));
                    int rq   = idx - slot * (KF * (XWW / 4));
                    int r    = rq / (XWW / 4);
                    int q    = rq - r * (XWW / 4);
                    int wl   = slot >> 1;
                    int ci   = slot & 1;
                    int c    = (8 * s + wl) * CPG + 2 * j + ci;
                    int yy   = y + r - PAD;
                    int col0 = x0 - 4 + q * 4;
                    float4 v = zero4;
                    if ((unsigned)yy < HH && (unsigned)col0 < WW)
                        v = *(const float4*)(x + ((size_t)(b * CC + c) * HH + yy) * WW + col0);
                    xw4[idx] = v;
                }
            }
            __syncthreads();

            if (lane < TW) {
                #pragma unroll
                for (int ci = 0; ci < 2; ci++) {
                    const float* wrow = xw + ((2 * warp + ci) * KF) * XWW + lane + 1;
                    float a0 = 0.f, a1 = 0.f;
                    #pragma unroll
                    for (int r = 0; r < KF; r++) {
                        #pragma unroll
                        for (int kw = 0; kw < KF; kw++) {
                            float v = wrow[r * XWW + kw];
                            if (kw & 1) a1 += kr[r * KF + kw] * v;
                            else        a0 += kr[r * KF + kw] * v;
                        }
                    }
                    const int c = g * CPG + 2 * j + ci;
                    out[((size_t)(b * CC + c) * HH + y) * WW + x0 + lane] = a0 + a1;
                }
            }
        }
        if (s == 0) __syncthreads();
    }
}

extern "C" void kernel_launch(void* const* d_in, const int* in_sizes, int n_in,
                              void* d_out, int out_size)
{
    const float* x  = (const float*)d_in[0];  // (4,256,56,56)
    const float* rw = (const float*)d_in[1];  // (64,256)
    const float* rb = (const float*)d_in[2];  // (64,)
    const float* sw = (const float*)d_in[3];  // (784,64)
    const float* sb = (const float*)d_in[4];  // (784,)
    float* out = (float*)d_out;

    prep_sw_kernel<<<(196 * 32 + 255) / 256, 256>>>(sw);

    const int smem_bytes = SMEM_FLOATS * (int)sizeof(float);  // 111104
    cudaFuncSetAttribute(inv_fused_kernel,
                         cudaFuncAttributeMaxDynamicSharedMemorySize, smem_bytes);
    dim3 grid(WW / TW, HH, BB);   // (2, 56, 4) = 448 blocks
    inv_fused_kernel<<<grid, NTHREADS, smem_bytes>>>(x, rw, rb, sb, out);
}

// round 9
// speedup vs baseline: 1.4902x; 1.4902x over previous
#include <cuda_runtime.h>
#include <cuda_bf16.h>
#include <cstdint>
#include <cstring>

// involution: B=4, C=256, G=16, K=7, S=1, P=3, R=4, H=W=56
#define BB    4
#define CC    256
#define GG    16
#define CPG   16
#define KF    7
#define PAD   3
#define HH    56
#define WW    56
#define SP    3136            // H*W
#define P_TOT 12544           // B*H*W
#define CR    64              // C/R
#define KK    49
#define KKG   784             // K*K*G
#define TW    28

// ---------------- device scratch ----------------
__device__ float g_h[CR * P_TOT];                    // 3.2 MB
__device__ float g_kern[KKG * P_TOT];                // 39.3 MB (L2-resident)
__device__ __align__(16) uint4 g_A[2][196][32];      // sw bf16 hi/lo A-fragments

__device__ __forceinline__ unsigned short bfbits(__nv_bfloat16 h) {
    unsigned short s; memcpy(&s, &h, 2); return s;
}
__device__ __forceinline__ void mma_bf16(float* c, const uint4& a,
                                         unsigned b0, unsigned b1) {
    asm volatile(
        "mma.sync.aligned.m16n8k16.row.col.f32.bf16.bf16.f32 "
        "{%0,%1,%2,%3}, {%4,%5,%6,%7}, {%8,%9}, {%0,%1,%2,%3};"
        : "+f"(c[0]), "+f"(c[1]), "+f"(c[2]), "+f"(c[3])
        : "r"(a.x), "r"(a.y), "r"(a.z), "r"(a.w), "r"(b0), "r"(b1));
}

// ---------------- prep: split sw into bf16 hi/lo A-fragments ----------------
__global__ void prep_sw_kernel(const float* __restrict__ sw)
{
    int i = blockIdx.x * blockDim.x + threadIdx.x;
    if (i >= 196 * 32) return;
    int tu = i >> 5, lane = i & 31;
    int t = tu >> 2, u = tu & 3;
    int r0 = t * 16 + (lane >> 2);
    int c0 = u * 16 + (lane & 3) * 2;
    const int rr[4] = {r0, r0 + 8, r0, r0 + 8};
    const int cc[4] = {c0, c0, c0 + 8, c0 + 8};
    unsigned hv[4], lv[4];
    #pragma unroll
    for (int j = 0; j < 4; j++) {
        float v0 = sw[rr[j] * CR + cc[j]];
        float v1 = sw[rr[j] * CR + cc[j] + 1];
        __nv_bfloat16 h0 = __float2bfloat16(v0);
        __nv_bfloat16 h1 = __float2bfloat16(v1);
        __nv_bfloat16 l0 = __float2bfloat16(v0 - __bfloat162float(h0));
        __nv_bfloat16 l1 = __float2bfloat16(v1 - __bfloat162float(h1));
        hv[j] = (unsigned)bfbits(h0) | ((unsigned)bfbits(h1) << 16);
        lv[j] = (unsigned)bfbits(l0) | ((unsigned)bfbits(l1) << 16);
    }
    g_A[0][tu][lane] = make_uint4(hv[0], hv[1], hv[2], hv[3]);
    g_A[1][tu][lane] = make_uint4(lv[0], lv[1], lv[2], lv[3]);
}

// ---------------- K1: h[64][P] = rw @ x + rb (scalar fp32) ----------------
// grid 196 (64-px tiles), 256 threads, smem: rws 64KB + xs 16KB
#define K1_SMEM (16384 + 4096) * 4
__global__ __launch_bounds__(256, 2)
void k1_reduce(const float* __restrict__ x,
               const float* __restrict__ rw,
               const float* __restrict__ rb)
{
    extern __shared__ float sm1[];
    float*  rws  = sm1;                  // [64][256]
    float*  xs   = sm1 + 16384;          // [64 c][64 px] per chunk
    float4* rws4 = (float4*)rws;
    float4* xs4  = (float4*)xs;

    const int tid  = threadIdx.x;
    const int warp = tid >> 5;
    const int lane = tid & 31;
    const int p0   = blockIdx.x * 64;
    const int b    = p0 / SP;
    const int s0   = p0 - b * SP;        // tile never crosses batch (3136%64==0)
    const int o0   = warp * 8;

    {   // stage rw
        const float4* rwg4 = (const float4*)rw;
        #pragma unroll
        for (int i = tid; i < 4096; i += 256) rws4[i] = rwg4[i];
    }

    float acc[8][2];
    #pragma unroll
    for (int j = 0; j < 8; j++) { acc[j][0] = 0.f; acc[j][1] = 0.f; }

    #pragma unroll 1
    for (int chunk = 0; chunk < 4; chunk++) {
        __syncthreads();                 // WAR on xs (and rws ready, chunk 0)
        {   // load xs: 64 channels x 16 quads
            const float* xb = x + ((size_t)(b * CC + chunk * 64)) * SP + s0;
            #pragma unroll
            for (int i = tid; i < 1024; i += 256) {
                int c = i >> 4, q = i & 15;
                xs4[i] = *(const float4*)(xb + (size_t)c * SP + q * 4);
            }
        }
        __syncthreads();

        #pragma unroll 2
        for (int cq = 0; cq < 16; cq++) {
            float4 w[8];
            #pragma unroll
            for (int j = 0; j < 8; j++)
                w[j] = rws4[(o0 + j) * 64 + chunk * 16 + cq];
            #pragma unroll
            for (int e = 0; e < 4; e++) {
                int c = cq * 4 + e;
                float xa = xs[c * 64 + lane];
                float xb2 = xs[c * 64 + lane + 32];
                #pragma unroll
                for (int j = 0; j < 8; j++) {
                    float we = (e == 0) ? w[j].x : (e == 1) ? w[j].y
                             : (e == 2) ? w[j].z : w[j].w;
                    acc[j][0] += we * xa;
                    acc[j][1] += we * xb2;
                }
            }
        }
    }

    #pragma unroll
    for (int j = 0; j < 8; j++) {
        float bias = __ldg(rb + o0 + j);
        g_h[(size_t)(o0 + j) * P_TOT + p0 + lane]      = acc[j][0] + bias;
        g_h[(size_t)(o0 + j) * P_TOT + p0 + lane + 32] = acc[j][1] + bias;
    }
}

// ---------------- K2: kern[784][P] = sw @ h + sb (HMMA bf16 hi/lo) ----------
// grid 196 (64-px tiles), 256 threads; smem: hb/lb panels [64 n][72 k] bf16
#define HSB 72
#define K2_SMEM (2 * 64 * HSB * 2)
__global__ __launch_bounds__(256, 2)
void k2_span(const float* __restrict__ sb)
{
    extern __shared__ __nv_bfloat16 sm2[];
    __nv_bfloat16* hb = sm2;                 // [64][72]
    __nv_bfloat16* lb = sm2 + 64 * HSB;      // [64][72]

    const int tid  = threadIdx.x;
    const int warp = tid >> 5;
    const int lane = tid & 31;
    const int p0   = blockIdx.x * 64;

    {   // build B panels from g_h (fp32 -> bf16 hi/lo), transposed [n][k]
        const int n  = tid & 63;
        const int kb = (tid >> 6) * 16;
        #pragma unroll
        for (int j = 0; j < 16; j++) {
            int k = kb + j;
            float v = g_h[(size_t)k * P_TOT + p0 + n];
            __nv_bfloat16 h = __float2bfloat16(v);
            __nv_bfloat16 l = __float2bfloat16(v - __bfloat162float(h));
            hb[n * HSB + k] = h;
            lb[n * HSB + k] = l;
        }
    }
    __syncthreads();

    #pragma unroll 1
    for (int t = warp; t < 49; t += 8) {
        uint4 ah[4], al[4];
        #pragma unroll
        for (int u = 0; u < 4; u++) {
            ah[u] = g_A[0][t * 4 + u][lane];
            al[u] = g_A[1][t * 4 + u][lane];
        }
        const int r0 = t * 16 + (lane >> 2);
        const float bias0 = __ldg(sb + r0);
        const float bias1 = __ldg(sb + r0 + 8);

        float acc[8][4];
        #pragma unroll
        for (int v = 0; v < 8; v++) {
            acc[v][0] = bias0; acc[v][1] = bias0;
            acc[v][2] = bias1; acc[v][3] = bias1;
        }

        #pragma unroll
        for (int v = 0; v < 8; v++) {
            const int n = v * 8 + (lane >> 2);
            const __nv_bfloat16* hrow = hb + n * HSB;
            const __nv_bfloat16* lrow = lb + n * HSB;
            #pragma unroll
            for (int u = 0; u < 4; u++) {
                const int k0 = u * 16 + (lane & 3) * 2;
                unsigned bh0 = *(const unsigned*)(hrow + k0);
                unsigned bh1 = *(const unsigned*)(hrow + k0 + 8);
                unsigned bl0 = *(const unsigned*)(lrow + k0);
                unsigned bl1 = *(const unsigned*)(lrow + k0 + 8);
                mma_bf16(acc[v], ah[u], bh0, bh1);
                mma_bf16(acc[v], ah[u], bl0, bl1);
                mma_bf16(acc[v], al[u], bh0, bh1);
            }
        }

        #pragma unroll
        for (int v = 0; v < 8; v++) {
            const int px0 = v * 8 + (lane & 3) * 2;
            *(float2*)(g_kern + (size_t)r0 * P_TOT + p0 + px0) =
                make_float2(acc[v][0], acc[v][1]);
            *(float2*)(g_kern + (size_t)(r0 + 8) * P_TOT + p0 + px0) =
                make_float2(acc[v][2], acc[v][3]);
        }
    }
}

// ---------------- K3: involution apply (warp-private windows, no barriers) --
// grid (2,56,4), 256 threads = 8 warps; smem 8 x [7][36] f32 = 32256 B
#define XWW 36
#define K3_SMEM (8 * KF * XWW * 4)
__global__ __launch_bounds__(256, 3)
void k3_apply(const float* __restrict__ x, float* __restrict__ out)
{
    extern __shared__ float sm3[];
    const int tid  = threadIdx.x;
    const int warp = tid >> 5;
    const int lane = tid & 31;
    const int x0   = blockIdx.x * TW;
    const int y    = blockIdx.y;
    const int b    = blockIdx.z;

    float*  xw  = sm3 + warp * (KF * XWW);   // private [7][36]
    float4* xw4 = (float4*)xw;
    const int pcol = b * SP + y * WW + x0 + lane;   // kern column

    #pragma unroll 1
    for (int s = 0; s < 2; s++) {
        const int g = 8 * s + warp;

        float kr[KK];
        if (lane < TW) {
            const float* kb = g_kern + (size_t)(g * KK) * P_TOT + pcol;
            #pragma unroll
            for (int t = 0; t < KK; t++) kr[t] = kb[(size_t)t * P_TOT];
        }

        #pragma unroll 1
        for (int ci = 0; ci < CPG; ci++) {
            const int c = g * CPG + ci;
            __syncwarp();                    // WAR: previous channel reads done
            {   // fill private window: 63 float4 (7 rows x 9 quads)
                const float* xrow = x + (size_t)(b * CC + c) * SP;
                #pragma unroll
                for (int i = lane; i < KF * (XWW / 4); i += 32) {
                    int r    = i / (XWW / 4);
                    int q    = i - r * (XWW / 4);
                    int yy   = y + r - PAD;
                    int col0 = x0 - 4 + q * 4;
                    float4 v = make_float4(0.f, 0.f, 0.f, 0.f);
                    if ((unsigned)yy < HH && (unsigned)col0 < WW)
                        v = *(const float4*)(xrow + yy * WW + col0);
                    xw4[i] = v;
                }
            }
            __syncwarp();

            if (lane < TW) {
                const float* wrow = xw + lane + 1;
                float a0 = 0.f, a1 = 0.f;
                #pragma unroll
                for (int r = 0; r < KF; r++) {
                    #pragma unroll
                    for (int kw = 0; kw < KF; kw++) {
                        float v = wrow[r * XWW + kw];
                        if (kw & 1) a1 += kr[r * KF + kw] * v;
                        else        a0 += kr[r * KF + kw] * v;
                    }
                }
                out[(size_t)(b * CC + c) * SP + y * WW + x0 + lane] = a0 + a1;
            }
        }
    }
}

// ---------------- launcher ----------------
extern "C" void kernel_launch(void* const* d_in, const int* in_sizes, int n_in,
                              void* d_out, int out_size)
{
    const float* x  = (const float*)d_in[0];  // (4,256,56,56)
    const float* rw = (const float*)d_in[1];  // (64,256)
    const float* rb = (const float*)d_in[2];  // (64,)
    const float* sw = (const float*)d_in[3];  // (784,64)
    const float* sb = (const float*)d_in[4];  // (784,)
    float* out = (float*)d_out;

    cudaFuncSetAttribute(k1_reduce, cudaFuncAttributeMaxDynamicSharedMemorySize, K1_SMEM);
    cudaFuncSetAttribute(k2_span,   cudaFuncAttributeMaxDynamicSharedMemorySize, K2_SMEM);
    cudaFuncSetAttribute(k3_apply,  cudaFuncAttributeMaxDynamicSharedMemorySize, K3_SMEM);

    prep_sw_kernel<<<25, 256>>>(sw);
    k1_reduce<<<P_TOT / 64, 256, K1_SMEM>>>(x, rw, rb);
    k2_span<<<P_TOT / 64, 256, K2_SMEM>>>(sb);
    k3_apply<<<dim3(WW / TW, HH, BB), 256, K3_SMEM>>>(x, out);
}

// round 10
// speedup vs baseline: 1.5176x; 1.0184x over previous
#include <cuda_runtime.h>
#include <cuda_bf16.h>
#include <cstdint>
#include <cstring>

// involution: B=4, C=256, G=16, K=7, S=1, P=3, R=4, H=W=56
#define BB    4
#define CC    256
#define GG    16
#define CPG   16
#define KF    7
#define PAD   3
#define HH    56
#define WW    56
#define SP    3136            // H*W
#define P_TOT 12544           // B*H*W
#define CR    64              // C/R
#define KK    49
#define KKG   784             // K*K*G
#define TW    28
#define XWW   36
#define WQ    (KF * XWW / 4)  // 63 quads per window

// ---------------- device scratch ----------------
__device__ float g_kern[KKG * P_TOT];                // 39.3 MB (L2-resident)
__device__ __align__(16) uint4 g_A[2][196][32];      // sw bf16 hi/lo A-fragments

__device__ __forceinline__ unsigned short bfbits(__nv_bfloat16 h) {
    unsigned short s; memcpy(&s, &h, 2); return s;
}
__device__ __forceinline__ void mma_bf16(float* c, const uint4& a,
                                         unsigned b0, unsigned b1) {
    asm volatile(
        "mma.sync.aligned.m16n8k16.row.col.f32.bf16.bf16.f32 "
        "{%0,%1,%2,%3}, {%4,%5,%6,%7}, {%8,%9}, {%0,%1,%2,%3};"
        : "+f"(c[0]), "+f"(c[1]), "+f"(c[2]), "+f"(c[3])
        : "r"(a.x), "r"(a.y), "r"(a.z), "r"(a.w), "r"(b0), "r"(b1));
}

// ---------------- prep: split sw into bf16 hi/lo A-fragments ----------------
__global__ void prep_sw_kernel(const float* __restrict__ sw)
{
    int i = blockIdx.x * blockDim.x + threadIdx.x;
    if (i >= 196 * 32) return;
    int tu = i >> 5, lane = i & 31;
    int t = tu >> 2, u = tu & 3;
    int r0 = t * 16 + (lane >> 2);
    int c0 = u * 16 + (lane & 3) * 2;
    const int rr[4] = {r0, r0 + 8, r0, r0 + 8};
    const int cc[4] = {c0, c0, c0 + 8, c0 + 8};
    unsigned hv[4], lv[4];
    #pragma unroll
    for (int j = 0; j < 4; j++) {
        float v0 = sw[rr[j] * CR + cc[j]];
        float v1 = sw[rr[j] * CR + cc[j] + 1];
        __nv_bfloat16 h0 = __float2bfloat16(v0);
        __nv_bfloat16 h1 = __float2bfloat16(v1);
        __nv_bfloat16 l0 = __float2bfloat16(v0 - __bfloat162float(h0));
        __nv_bfloat16 l1 = __float2bfloat16(v1 - __bfloat162float(h1));
        hv[j] = (unsigned)bfbits(h0) | ((unsigned)bfbits(h1) << 16);
        lv[j] = (unsigned)bfbits(l0) | ((unsigned)bfbits(l1) << 16);
    }
    g_A[0][tu][lane] = make_uint4(hv[0], hv[1], hv[2], hv[3]);
    g_A[1][tu][lane] = make_uint4(lv[0], lv[1], lv[2], lv[3]);
}

// ---------------- K12: h = rw@x+rb (scalar) -> smem panels -> HMMA -> g_kern
// grid 196 (64-px tiles), 256 threads
// smem: rws [64][256] f32 (64KB) | xs [64][64] f32 (16KB) | hb/lb [64][72] bf16 (18KB)
#define HSB       72
#define XS_F      16384
#define PAN_F     20480
#define K12_SMEM  (20480 * 4 + 2 * 64 * HSB * 2)    // 100352 B
__global__ __launch_bounds__(256, 2)
void k12_gen(const float* __restrict__ x,
             const float* __restrict__ rw,
             const float* __restrict__ rb,
             const float* __restrict__ sb)
{
    extern __shared__ float sm1[];
    float*  rws  = sm1;                          // [64][256]
    float*  xs   = sm1 + XS_F;                   // [64 c][64 px]
    __nv_bfloat16* hb = (__nv_bfloat16*)(sm1 + PAN_F);   // [64][72]
    __nv_bfloat16* lb = hb + 64 * HSB;                   // [64][72]
    float4* rws4 = (float4*)rws;
    float4* xs4  = (float4*)xs;

    const int tid  = threadIdx.x;
    const int warp = tid >> 5;
    const int lane = tid & 31;
    const int p0   = blockIdx.x * 64;
    const int b    = p0 / SP;
    const int s0   = p0 - b * SP;        // 3136 % 64 == 0: no batch crossing
    const int o0   = warp * 8;

    {   // stage rw
        const float4* rwg4 = (const float4*)rw;
        #pragma unroll
        for (int i = tid; i < 4096; i += 256) rws4[i] = rwg4[i];
    }

    // ---- Phase A: scalar reduce GEMM ----
    float acc[8][2];
    #pragma unroll
    for (int j = 0; j < 8; j++) { acc[j][0] = 0.f; acc[j][1] = 0.f; }

    #pragma unroll 1
    for (int chunk = 0; chunk < 4; chunk++) {
        __syncthreads();                 // WAR on xs (chunk 0: rws ready too)
        {
            const float* xb = x + ((size_t)(b * CC + chunk * 64)) * SP + s0;
            #pragma unroll
            for (int i = tid; i < 1024; i += 256) {
                int c = i >> 4, q = i & 15;
                xs4[i] = *(const float4*)(xb + (size_t)c * SP + q * 4);
            }
        }
        __syncthreads();

        #pragma unroll 2
        for (int cq = 0; cq < 16; cq++) {
            float4 w[8];
            #pragma unroll
            for (int j = 0; j < 8; j++)
                w[j] = rws4[(o0 + j) * 64 + chunk * 16 + cq];
            #pragma unroll
            for (int e = 0; e < 4; e++) {
                int c = cq * 4 + e;
                float xa  = xs[c * 64 + lane];
                float xb2 = xs[c * 64 + lane + 32];
                #pragma unroll
                for (int j = 0; j < 8; j++) {
                    float we = (e == 0) ? w[j].x : (e == 1) ? w[j].y
                             : (e == 2) ? w[j].z : w[j].w;
                    acc[j][0] += we * xa;
                    acc[j][1] += we * xb2;
                }
            }
        }
    }

    // ---- write bf16 hi/lo panels directly (transposed [n px][k o]) ----
    #pragma unroll
    for (int j = 0; j < 8; j++) {
        float bias = __ldg(rb + o0 + j);
        float v0 = acc[j][0] + bias;
        float v1 = acc[j][1] + bias;
        __nv_bfloat16 h0 = __float2bfloat16(v0);
        __nv_bfloat16 h1 = __float2bfloat16(v1);
        hb[lane * HSB + o0 + j]        = h0;
        hb[(lane + 32) * HSB + o0 + j] = h1;
        lb[lane * HSB + o0 + j]        = __float2bfloat16(v0 - __bfloat162float(h0));
        lb[(lane + 32) * HSB + o0 + j] = __float2bfloat16(v1 - __bfloat162float(h1));
    }
    __syncthreads();

    // ---- Phase B: HMMA span GEMM -> g_kern ----
    #pragma unroll 1
    for (int t = warp; t < 49; t += 8) {
        uint4 ah[4], al[4];
        #pragma unroll
        for (int u = 0; u < 4; u++) {
            ah[u] = g_A[0][t * 4 + u][lane];
            al[u] = g_A[1][t * 4 + u][lane];
        }
        const int r0 = t * 16 + (lane >> 2);
        const float bias0 = __ldg(sb + r0);
        const float bias1 = __ldg(sb + r0 + 8);

        float facc[8][4];
        #pragma unroll
        for (int v = 0; v < 8; v++) {
            facc[v][0] = bias0; facc[v][1] = bias0;
            facc[v][2] = bias1; facc[v][3] = bias1;
        }

        #pragma unroll
        for (int v = 0; v < 8; v++) {
            const int n = v * 8 + (lane >> 2);
            const __nv_bfloat16* hrow = hb + n * HSB;
            const __nv_bfloat16* lrow = lb + n * HSB;
            #pragma unroll
            for (int u = 0; u < 4; u++) {
                const int k0 = u * 16 + (lane & 3) * 2;
                unsigned bh0 = *(const unsigned*)(hrow + k0);
                unsigned bh1 = *(const unsigned*)(hrow + k0 + 8);
                unsigned bl0 = *(const unsigned*)(lrow + k0);
                unsigned bl1 = *(const unsigned*)(lrow + k0 + 8);
                mma_bf16(facc[v], ah[u], bh0, bh1);
                mma_bf16(facc[v], ah[u], bl0, bl1);
                mma_bf16(facc[v], al[u], bh0, bh1);
            }
        }

        #pragma unroll
        for (int v = 0; v < 8; v++) {
            const int px0 = v * 8 + (lane & 3) * 2;
            *(float2*)(g_kern + (size_t)r0 * P_TOT + p0 + px0) =
                make_float2(facc[v][0], facc[v][1]);
            *(float2*)(g_kern + (size_t)(r0 + 8) * P_TOT + p0 + px0) =
                make_float2(facc[v][2], facc[v][3]);
        }
    }
}

// ---------------- K3: involution apply (pipelined warp-private windows) ----
// grid (2,56,4), 256 thr = 8 warps; smem 8 warps x 2 bufs x [7][36] = 16128 B
#define K3_SMEM (8 * 2 * KF * XWW * 4)
__global__ __launch_bounds__(256, 3)
void k3_apply(const float* __restrict__ x, float* __restrict__ out)
{
    extern __shared__ float sm3[];
    const int tid  = threadIdx.x;
    const int warp = tid >> 5;
    const int lane = tid & 31;
    const int x0   = blockIdx.x * TW;
    const int y    = blockIdx.y;
    const int b    = blockIdx.z;

    float* wbase = sm3 + warp * (2 * KF * XWW);
    const int pcol = b * SP + y * WW + x0 + lane;

    // per-lane window-fill coordinates (quads i = lane, lane+32)
    const int i0 = lane;
    const int r0q = i0 / (XWW / 4), q0 = i0 - r0q * (XWW / 4);
    const int yy0 = y + r0q - PAD,  c00 = x0 - 4 + q0 * 4;
    const bool ok0 = ((unsigned)yy0 < HH) && ((unsigned)c00 < WW);
    const int i1 = lane + 32;
    const int r1q = i1 / (XWW / 4), q1 = i1 - r1q * (XWW / 4);
    const int yy1 = y + r1q - PAD,  c10 = x0 - 4 + q1 * 4;
    const bool ok1 = (i1 < WQ) && ((unsigned)yy1 < HH) && ((unsigned)c10 < WW);

    #pragma unroll 1
    for (int s = 0; s < 2; s++) {
        const int g = 8 * s + warp;

        float kr[KK];
        if (lane < TW) {
            const float* kb = g_kern + (size_t)(g * KK) * P_TOT + pcol;
            #pragma unroll
            for (int t = 0; t < KK; t++) kr[t] = kb[(size_t)t * P_TOT];
        }

        // prefetch channel 0 of this group
        const int cbase = g * CPG;
        float4 pf0 = make_float4(0.f, 0.f, 0.f, 0.f), pf1 = pf0;
        {
            const float* xr = x + (size_t)(b * CC + cbase) * SP;
            if (ok0) pf0 = *(const float4*)(xr + yy0 * WW + c00);
            if (ok1) pf1 = *(const float4*)(xr + yy1 * WW + c10);
        }

        #pragma unroll 1
        for (int ci = 0; ci < CPG; ci++) {
            float*  buf  = wbase + (ci & 1) * (KF * XWW);
            float4* buf4 = (float4*)buf;
            buf4[i0] = pf0;
            if (i1 < WQ) buf4[i1] = pf1;
            __syncwarp();

            if (ci + 1 < CPG) {   // prefetch next channel (latency hidden by compute)
                const float* xr = x + (size_t)(b * CC + cbase + ci + 1) * SP;
                pf0 = ok0 ? *(const float4*)(xr + yy0 * WW + c00)
                          : make_float4(0.f, 0.f, 0.f, 0.f);
                pf1 = ok1 ? *(const float4*)(xr + yy1 * WW + c10)
                          : make_float4(0.f, 0.f, 0.f, 0.f);
            }

            if (lane < TW) {
                const float* wrow = buf + lane + 1;
                float a0 = 0.f, a1 = 0.f;
                #pragma unroll
                for (int r = 0; r < KF; r++) {
                    #pragma unroll
                    for (int kw = 0; kw < KF; kw++) {
                        float v = wrow[r * XWW + kw];
                        if (kw & 1) a1 += kr[r * KF + kw] * v;
                        else        a0 += kr[r * KF + kw] * v;
                    }
                }
                out[(size_t)(b * CC + cbase + ci) * SP + y * WW + x0 + lane] = a0 + a1;
            }
        }
    }
}

// ---------------- launcher ----------------
extern "C" void kernel_launch(void* const* d_in, const int* in_sizes, int n_in,
                              void* d_out, int out_size)
{
    const float* x  = (const float*)d_in[0];  // (4,256,56,56)
    const float* rw = (const float*)d_in[1];  // (64,256)
    const float* rb = (const float*)d_in[2];  // (64,)
    const float* sw = (const float*)d_in[3];  // (784,64)
    const float* sb = (const float*)d_in[4];  // (784,)
    float* out = (float*)d_out;

    cudaFuncSetAttribute(k12_gen, cudaFuncAttributeMaxDynamicSharedMemorySize, K12_SMEM);
    cudaFuncSetAttribute(k3_apply, cudaFuncAttributeMaxDynamicSharedMemorySize, K3_SMEM);

    prep_sw_kernel<<<25, 256>>>(sw);
    k12_gen<<<P_TOT / 64, 256, K12_SMEM>>>(x, rw, rb, sb);
    k3_apply<<<dim3(WW / TW, HH, BB), 256, K3_SMEM>>>(x, out);
}